// round 8
// baseline (speedup 1.0000x reference)
#include <cuda_runtime.h>
#include <cstdint>

// sbvr decode:
//   out[g*16 + l] = sum_s coeff_cache[coeff_idx[g]][s] * ((bvr[g][s] >> l) & 1)
// G = 4,194,304 groups, S = 4, L = 16.
//
// R7 -> R8: occupancy 66->89% moved nothing (L1 pinned ~72%, DRAM ~63%) =>
// warp-independent ceiling. Experiment/win: remove the 256MB store stream
// from the L1/LSU wavefront path. Warp-contiguous remap (each warp owns a
// contiguous 4KB gmem span), results staged in smem (STS.128, conflict-free),
// shipped by ONE cp.async.bulk.global.shared::cta (UBLKCP, TMA engine - idle
// until now) per warp. One syncwarp+fence+wait per warp LIFETIME.
// Gather pipeline + pipe-balanced asm decode unchanged.

static constexpr unsigned QT_TOTAL = 16u * 1024u * 1024u;  // 4M groups * 4 quarters
static constexpr int      BLOCK    = 256;
static constexpr int      ITER     = 8;                    // quarter-groups per thread
static constexpr unsigned BLOCKS   = QT_TOTAL / (BLOCK * ITER);  // 8192
static constexpr int      GSTRIDE  = 8;                    // groups per warp-iteration

// Pipe-balanced decode: lop3 with predicate output (ALU; AND+test in one op)
// feeding predicated add.f32 (FMA pipe). Exact fp32 -> rel_err 0.
__device__ __forceinline__ float4 decode_quarter(int4 w, float4 c, unsigned m0)
{
    float4 r;
    asm(
    "{\n\t"
    ".reg .pred q, p0, p1, p2, p3;\n\t"
    ".reg .b32  t, m1, m2, m3;\n\t"
    "setp.ne.u32 q, %4, %4;\n\t"
    "shl.b32 m1, %8, 1;\n\t"
    "shl.b32 m2, %8, 2;\n\t"
    "shl.b32 m3, %8, 3;\n\t"
    // ---- element 0 ----
    "lop3.or.b32 t|p0, %4, %8, %4, 0xC0, q;\n\t"
    "lop3.or.b32 t|p1, %5, %8, %5, 0xC0, q;\n\t"
    "lop3.or.b32 t|p2, %6, %8, %6, 0xC0, q;\n\t"
    "lop3.or.b32 t|p3, %7, %8, %7, 0xC0, q;\n\t"
    "selp.f32 %0, %9, 0f00000000, p0;\n\t"
    "@p1 add.rn.f32 %0, %0, %10;\n\t"
    "@p2 add.rn.f32 %0, %0, %11;\n\t"
    "@p3 add.rn.f32 %0, %0, %12;\n\t"
    // ---- element 1 ----
    "lop3.or.b32 t|p0, %4, m1, %4, 0xC0, q;\n\t"
    "lop3.or.b32 t|p1, %5, m1, %5, 0xC0, q;\n\t"
    "lop3.or.b32 t|p2, %6, m1, %6, 0xC0, q;\n\t"
    "lop3.or.b32 t|p3, %7, m1, %7, 0xC0, q;\n\t"
    "selp.f32 %1, %9, 0f00000000, p0;\n\t"
    "@p1 add.rn.f32 %1, %1, %10;\n\t"
    "@p2 add.rn.f32 %1, %1, %11;\n\t"
    "@p3 add.rn.f32 %1, %1, %12;\n\t"
    // ---- element 2 ----
    "lop3.or.b32 t|p0, %4, m2, %4, 0xC0, q;\n\t"
    "lop3.or.b32 t|p1, %5, m2, %5, 0xC0, q;\n\t"
    "lop3.or.b32 t|p2, %6, m2, %6, 0xC0, q;\n\t"
    "lop3.or.b32 t|p3, %7, m2, %7, 0xC0, q;\n\t"
    "selp.f32 %2, %9, 0f00000000, p0;\n\t"
    "@p1 add.rn.f32 %2, %2, %10;\n\t"
    "@p2 add.rn.f32 %2, %2, %11;\n\t"
    "@p3 add.rn.f32 %2, %2, %12;\n\t"
    // ---- element 3 ----
    "lop3.or.b32 t|p0, %4, m3, %4, 0xC0, q;\n\t"
    "lop3.or.b32 t|p1, %5, m3, %5, 0xC0, q;\n\t"
    "lop3.or.b32 t|p2, %6, m3, %6, 0xC0, q;\n\t"
    "lop3.or.b32 t|p3, %7, m3, %7, 0xC0, q;\n\t"
    "selp.f32 %3, %9, 0f00000000, p0;\n\t"
    "@p1 add.rn.f32 %3, %3, %10;\n\t"
    "@p2 add.rn.f32 %3, %3, %11;\n\t"
    "@p3 add.rn.f32 %3, %3, %12;\n\t"
    "}\n\t"
    : "=f"(r.x), "=f"(r.y), "=f"(r.z), "=f"(r.w)
    : "r"(w.x), "r"(w.y), "r"(w.z), "r"(w.w),
      "r"(m0),
      "f"(c.x), "f"(c.y), "f"(c.z), "f"(c.w));
    return r;
}

__global__ __launch_bounds__(BLOCK, 6) void sbvr_kernel(
    const float4* __restrict__ coeff_cache,   // [65536] rows of 4 floats
    const int*    __restrict__ coeff_idx,     // [G]
    const int4*   __restrict__ bvr,           // [G]
    float4*       __restrict__ out)           // [4*G]
{
    __shared__ float4 stage[BLOCK * ITER];    // 32KB; warp w owns stage[w*256 .. +256)

    unsigned lane = threadIdx.x & 31u;
    unsigned wrp  = threadIdx.x >> 5;

    // Warp-contiguous mapping: warp w owns quarter-indices
    // [block*2048 + w*256, +256); iteration i covers +i*32.
    unsigned qbase = blockIdx.x * (unsigned)(BLOCK * ITER) + wrp * (32u * ITER);
    unsigned gbase = (qbase >> 2) + (lane >> 2);

    const int*  ip = coeff_idx + gbase;
    const int4* wp = bvr + gbase;

    unsigned m0 = 1u << ((lane & 3u) * 4u);   // invariant over i

    float4* sl = stage + wrp * (32u * ITER) + lane;  // + i*32 per iter

    // Rolling pipeline: idx prefetch distance 2, bvr distance 1, gather distance 1.
    int    ci1 = __ldcs(ip);
    int    ci2 = __ldcs(ip + GSTRIDE);
    int4   w0  = __ldcs(wp);
    float4 c_cur = __ldcg(coeff_cache + ci1);

    #pragma unroll
    for (int i = 0; i < ITER; i++) {
        int ci_next = ci2;
        if (i + 2 < ITER)
            ci2 = __ldcs(ip + (i + 2) * GSTRIDE);

        int4 w1 = w0;
        if (i + 1 < ITER)
            w1 = __ldcs(wp + (i + 1) * GSTRIDE);

        float4 c_nxt = c_cur;
        if (i + 1 < ITER)
            c_nxt = __ldcg(coeff_cache + ci_next);

        sl[i * 32] = decode_quarter(w0, c_cur, m0);   // STS.128, conflict-free

        w0 = w1;
        c_cur = c_nxt;
        ci1 = ci_next; (void)ci1;
    }

    // Ship the warp's 4KB staged tile via the TMA/bulk engine (once per warp).
    __syncwarp();                                     // lanes' STS -> lane0's proxy op
    asm volatile("fence.proxy.async.shared::cta;" ::: "memory");
    if (lane == 0) {
        uint32_t saddr;
        asm("{ .reg .u64 t; cvta.to.shared.u64 t, %1; cvt.u32.u64 %0, t; }"
            : "=r"(saddr) : "l"(stage + wrp * (32u * ITER)));
        const float4* gdst = out + qbase;
        asm volatile(
            "cp.async.bulk.global.shared::cta.bulk_group [%0], [%1], %2;\n\t"
            "cp.async.bulk.commit_group;"
            :: "l"(gdst), "r"(saddr), "r"(32 * ITER * 16) : "memory");
        asm volatile("cp.async.bulk.wait_group 0;" ::: "memory");
    }
}

extern "C" void kernel_launch(void* const* d_in, const int* in_sizes, int n_in,
                              void* d_out, int out_size)
{
    const float4* coeff_cache = (const float4*)d_in[0];  // [65536,4] f32
    const int*    coeff_idx   = (const int*)d_in[1];     // [G] i32
    const int4*   bvr         = (const int4*)d_in[2];    // [G,4] i32
    float4*       out         = (float4*)d_out;          // [8192,8192] f32

    (void)in_sizes; (void)n_in; (void)out_size;

    sbvr_kernel<<<BLOCKS, BLOCK>>>(coeff_cache, coeff_idx, bvr, out);
}

// round 10
// speedup vs baseline: 1.4267x; 1.4267x over previous
#include <cuda_runtime.h>
#include <cstdint>

// sbvr decode:
//   out[g*16 + l] = sum_s coeff_cache[coeff_idx[g]][s] * ((bvr[g][s] >> l) & 1)
// G = 4,194,304 groups, S = 4, L = 16.
//
// R9 (resubmit; previous bench run hit a container-acquisition infra failure,
// kernel itself untested): deep software pipeline on the R6 skeleton.
// Limiter: per-warp idx(~1000cyc DRAM) -> gather(~400cyc L2) chain, formerly
// only 2+1 deep. Now ITER=16 with idx prefetch distance 6, bvr 3, gather 3:
// per-warp iteration period ~ max(1000/6, 400/3, issue) ~ 170cyc.
// Arrays fully unrolled -> SSA; peak live pipeline state ~30 regs, fits the
// __launch_bounds__(256,5) 51-reg budget without spills.

static constexpr unsigned QT_TOTAL = 16u * 1024u * 1024u;  // 4M groups * 4 quarters
static constexpr int      BLOCK    = 256;
static constexpr int      ITER     = 16;                   // quarter-groups per thread
static constexpr int      PF_I     = 6;                    // idx prefetch distance
static constexpr int      PF_W     = 3;                    // bvr prefetch distance
static constexpr int      PF_C     = 3;                    // gather prefetch distance
static constexpr unsigned BLOCKS   = QT_TOTAL / (BLOCK * ITER);  // 4096
static constexpr int      GSTRIDE  = BLOCK / 4;            // 64 groups per iteration

// Pipe-balanced decode: lop3 with predicate output (ALU; AND+test in one op)
// feeding predicated add.f32 (FMA pipe). Exact fp32 -> rel_err 0.
__device__ __forceinline__ float4 decode_quarter(int4 w, float4 c, unsigned m0)
{
    float4 r;
    asm(
    "{\n\t"
    ".reg .pred q, p0, p1, p2, p3;\n\t"
    ".reg .b32  t, m1, m2, m3;\n\t"
    "setp.ne.u32 q, %4, %4;\n\t"
    "shl.b32 m1, %8, 1;\n\t"
    "shl.b32 m2, %8, 2;\n\t"
    "shl.b32 m3, %8, 3;\n\t"
    // ---- element 0 ----
    "lop3.or.b32 t|p0, %4, %8, %4, 0xC0, q;\n\t"
    "lop3.or.b32 t|p1, %5, %8, %5, 0xC0, q;\n\t"
    "lop3.or.b32 t|p2, %6, %8, %6, 0xC0, q;\n\t"
    "lop3.or.b32 t|p3, %7, %8, %7, 0xC0, q;\n\t"
    "selp.f32 %0, %9, 0f00000000, p0;\n\t"
    "@p1 add.rn.f32 %0, %0, %10;\n\t"
    "@p2 add.rn.f32 %0, %0, %11;\n\t"
    "@p3 add.rn.f32 %0, %0, %12;\n\t"
    // ---- element 1 ----
    "lop3.or.b32 t|p0, %4, m1, %4, 0xC0, q;\n\t"
    "lop3.or.b32 t|p1, %5, m1, %5, 0xC0, q;\n\t"
    "lop3.or.b32 t|p2, %6, m1, %6, 0xC0, q;\n\t"
    "lop3.or.b32 t|p3, %7, m1, %7, 0xC0, q;\n\t"
    "selp.f32 %1, %9, 0f00000000, p0;\n\t"
    "@p1 add.rn.f32 %1, %1, %10;\n\t"
    "@p2 add.rn.f32 %1, %1, %11;\n\t"
    "@p3 add.rn.f32 %1, %1, %12;\n\t"
    // ---- element 2 ----
    "lop3.or.b32 t|p0, %4, m2, %4, 0xC0, q;\n\t"
    "lop3.or.b32 t|p1, %5, m2, %5, 0xC0, q;\n\t"
    "lop3.or.b32 t|p2, %6, m2, %6, 0xC0, q;\n\t"
    "lop3.or.b32 t|p3, %7, m2, %7, 0xC0, q;\n\t"
    "selp.f32 %2, %9, 0f00000000, p0;\n\t"
    "@p1 add.rn.f32 %2, %2, %10;\n\t"
    "@p2 add.rn.f32 %2, %2, %11;\n\t"
    "@p3 add.rn.f32 %2, %2, %12;\n\t"
    // ---- element 3 ----
    "lop3.or.b32 t|p0, %4, m3, %4, 0xC0, q;\n\t"
    "lop3.or.b32 t|p1, %5, m3, %5, 0xC0, q;\n\t"
    "lop3.or.b32 t|p2, %6, m3, %6, 0xC0, q;\n\t"
    "lop3.or.b32 t|p3, %7, m3, %7, 0xC0, q;\n\t"
    "selp.f32 %3, %9, 0f00000000, p0;\n\t"
    "@p1 add.rn.f32 %3, %3, %10;\n\t"
    "@p2 add.rn.f32 %3, %3, %11;\n\t"
    "@p3 add.rn.f32 %3, %3, %12;\n\t"
    "}\n\t"
    : "=f"(r.x), "=f"(r.y), "=f"(r.z), "=f"(r.w)
    : "r"(w.x), "r"(w.y), "r"(w.z), "r"(w.w),
      "r"(m0),
      "f"(c.x), "f"(c.y), "f"(c.z), "f"(c.w));
    return r;
}

__global__ __launch_bounds__(BLOCK, 5) void sbvr_kernel(
    const float4* __restrict__ coeff_cache,   // [65536] rows of 4 floats
    const int*    __restrict__ coeff_idx,     // [G]
    const int4*   __restrict__ bvr,           // [G]
    float4*       __restrict__ out)           // [4*G]
{
    // Block-contiguous tile: quarter-indices [b*BLOCK*ITER, ...), iteration i
    // at +i*BLOCK. All per-iteration offsets are small immediates.
    unsigned t = blockIdx.x * (unsigned)(BLOCK * ITER) + threadIdx.x;
    unsigned g = t >> 2;

    const int*  ip = coeff_idx + g;
    const int4* wp = bvr + g;
    float4*     op = out + t;

    unsigned m0 = 1u << ((t & 3u) * 4u);   // BLOCK % 4 == 0: invariant over i

    int    ci[ITER];
    int4   w [ITER];
    float4 c [ITER];

    // Prologue: fill all three prefetch streams to their distances.
    #pragma unroll
    for (int i = 0; i < PF_I; i++)
        ci[i] = __ldcs(ip + i * GSTRIDE);
    #pragma unroll
    for (int i = 0; i < PF_W; i++)
        w[i] = __ldcs(wp + i * GSTRIDE);
    #pragma unroll
    for (int i = 0; i < PF_C; i++)
        c[i] = __ldcg(coeff_cache + ci[i]);

    #pragma unroll
    for (int i = 0; i < ITER; i++) {
        if (i + PF_I < ITER)                      // idx for iter i+6
            ci[i + PF_I] = __ldcs(ip + (i + PF_I) * GSTRIDE);
        if (i + PF_W < ITER)                      // bvr for iter i+3
            w[i + PF_W] = __ldcs(wp + (i + PF_W) * GSTRIDE);
        if (i + PF_C < ITER)                      // gather for iter i+3 (idx landed 3 iters ago)
            c[i + PF_C] = __ldcg(coeff_cache + ci[i + PF_C]);

        float4 r = decode_quarter(w[i], c[i], m0);
        __stcs(op + i * BLOCK, r);
    }
}

extern "C" void kernel_launch(void* const* d_in, const int* in_sizes, int n_in,
                              void* d_out, int out_size)
{
    const float4* coeff_cache = (const float4*)d_in[0];  // [65536,4] f32
    const int*    coeff_idx   = (const int*)d_in[1];     // [G] i32
    const int4*   bvr         = (const int4*)d_in[2];    // [G,4] i32
    float4*       out         = (float4*)d_out;          // [8192,8192] f32

    (void)in_sizes; (void)n_in; (void)out_size;

    sbvr_kernel<<<BLOCKS, BLOCK>>>(coeff_cache, coeff_idx, bvr, out);
}